// round 2
// baseline (speedup 1.0000x reference)
#include <cuda_runtime.h>
#include <math.h>

#define NQ0 1000
#define NQ1 500
#define MP  512          // padded+bordered Schur dim: 500 S + 11 identity + 1 border(u)
#define G0P 1024
#define NB  64
#define NPAN (MP/NB)     // 8
#define CL  8            // cluster size
#define NMAX 8192
#define UROW (MP-1)      // 511: border row holding u

// ---------------- device scratch ----------------
static __device__ float g_S[MP*MP];
static __device__ float g_n0[G0P], g_s0[G0P], g_w0[G0P], g_ws0[G0P];
static __device__ float g_n1[MP],  g_s1[MP];
static __device__ int   g_off[G0P+1];
static __device__ int   g_cur[G0P];
static __device__ unsigned short g_csr[NMAX];
static __device__ int   g_i0[NMAX], g_i1[NMAX];
static __device__ double g_rTr, g_ldD0, g_q0;

#define CLUSTER_SYNC() do { \
    asm volatile("barrier.cluster.arrive.aligned;" ::: "memory"); \
    asm volatile("barrier.cluster.wait.aligned;"   ::: "memory"); } while (0)

// ---------------- K1: zero scratch ----------------
__global__ void k_zero() {
    int i = blockIdx.x * blockDim.x + threadIdx.x;
    int stride = gridDim.x * blockDim.x;
    for (int t = i; t < MP*MP; t += stride) g_S[t] = 0.f;
    if (i < G0P) { g_n0[i] = 0.f; g_s0[i] = 0.f; g_cur[i] = 0; }
    if (i < MP)  { g_n1[i] = 0.f; g_s1[i] = 0.f; }
}

// ---------------- K2: fused scatter/prep/scan/csr/pairs (single block 1024) -
__global__ __launch_bounds__(1024) void k_fuse(
        const float* __restrict__ yt, const float* __restrict__ yp,
        const void* z0, const void* z1,
        const float* __restrict__ sig2e, const float* __restrict__ sig2bs, int n) {
    __shared__ int sm[G0P];
    __shared__ int s_is64;
    __shared__ double sred[3][32];
    int tid = threadIdx.x;

    // detect int64 vs int32 indices (high 32-bit words all zero)
    if (tid == 0) {
        const unsigned int* w = (const unsigned int*)z0;
        int all0 = 1;
        for (int k = 1; k < 128; k += 2) if (w[k]) { all0 = 0; break; }
        s_is64 = all0;
    }
    __syncthreads();
    int is64 = s_is64;

    // --- scatter: counts, group sums, rTr ---
    double rtr = 0.0;
    for (int i = tid; i < n && i < NMAX; i += 1024) {
        float r = yt[i] - yp[i];
        int a, b;
        if (is64) { a = (int)((const long long*)z0)[i]; b = (int)((const long long*)z1)[i]; }
        else      { a = ((const int*)z0)[i];            b = ((const int*)z1)[i]; }
        if ((unsigned)a < (unsigned)NQ0 && (unsigned)b < (unsigned)NQ1) {
            g_i0[i] = a; g_i1[i] = b;
            atomicAdd(&g_n0[a], 1.f); atomicAdd(&g_s0[a], r);
            atomicAdd(&g_n1[b], 1.f); atomicAdd(&g_s1[b], r);
            rtr += (double)r * (double)r;
        } else { g_i0[i] = 0; g_i1[i] = 0; }
    }
    __syncthreads();

    // --- prep: w0, logdet(D0), q0, S diag + u row base ---
    float e = sig2e[0], b0 = sig2bs[0], b1 = sig2bs[1];
    float sqb1 = sqrtf(b1);
    double ld = 0.0, q = 0.0;
    for (int i = tid; i < G0P + MP; i += 1024) {
        if (i < G0P) {
            float d0 = e + b0 * g_n0[i];
            float w  = 1.f / d0;
            g_w0[i] = w; g_ws0[i] = g_s0[i] * w;
            if (i < NQ0) {
                ld += log((double)d0);
                q  += (double)b0 * (double)g_s0[i] * (double)g_s0[i] * (double)w;
            }
        } else {
            int j = i - G0P;
            if (j < NQ1) {
                g_S[j*MP + j] = e + b1 * g_n1[j];
                g_S[UROW*MP + j] = sqb1 * g_s1[j];      // border row = u
            } else if (j < UROW) {
                g_S[j*MP + j] = 1.f;                    // identity padding
            }                                           // S[511][511] stays 0
        }
    }
    __syncthreads();

    // --- scan over group-0 counts (Hillis-Steele, 1024 threads) ---
    sm[tid] = (int)g_n0[tid];
    __syncthreads();
    for (int d = 1; d < G0P; d <<= 1) {
        int v = (tid >= d) ? sm[tid - d] : 0;
        __syncthreads();
        sm[tid] += v;
        __syncthreads();
    }
    g_off[tid + 1] = sm[tid];
    if (tid == 0) g_off[0] = 0;
    __syncthreads();

    // --- csr build + u correction (atomics into border row) ---
    float ucoef = -sqb1 * b0;
    for (int i = tid; i < n && i < NMAX; i += 1024) {
        int a = g_i0[i], b = g_i1[i];
        int p = atomicAdd(&g_cur[a], 1);
        g_csr[g_off[a] + p] = (unsigned short)b;
        atomicAdd(&g_S[UROW*MP + b], ucoef * g_ws0[a]);
    }
    __syncthreads();

    // --- pairs: S -= b0*b1 * C^T D0^{-1} C (sparse all-pairs per group) ---
    int wid = tid >> 5, lane = tid & 31;
    for (int g = wid; g < NQ0; g += 32) {
        int lo = g_off[g], len = g_off[g + 1] - lo;
        if (!len) continue;
        float coef = -b0 * b1 * g_w0[g];
        int tot = len * len;
        for (int t = lane; t < tot; t += 32) {
            int a = g_csr[lo + t / len];
            int b = g_csr[lo + t % len];
            atomicAdd(&g_S[a * MP + b], coef);
        }
    }

    // --- reduce rtr, ld, q -> globals ---
    #pragma unroll
    for (int o = 16; o; o >>= 1) {
        rtr += __shfl_down_sync(0xffffffffu, rtr, o);
        ld  += __shfl_down_sync(0xffffffffu, ld,  o);
        q   += __shfl_down_sync(0xffffffffu, q,   o);
    }
    if (lane == 0) { sred[0][wid] = rtr; sred[1][wid] = ld; sred[2][wid] = q; }
    __syncthreads();
    if (tid == 0) {
        double a0 = 0, a1 = 0, a2 = 0;
        for (int k = 0; k < 32; k++) { a0 += sred[0][k]; a1 += sred[1][k]; a2 += sred[2][k]; }
        g_rTr = a0; g_ldD0 = a1; g_q0 = a2;
    }
}

// ---------------- K3: single-launch clustered Cholesky + loss --------------
__global__ void __cluster_dims__(CL,1,1) __launch_bounds__(256,1)
k_chol(const float* __restrict__ sig2e, float* __restrict__ out, int n) {
    __shared__ float Ld[NB][NB + 1];
    __shared__ float B [NB][NB + 1];
    __shared__ float dinv[NB];
    int rank = blockIdx.x;
    int tid = threadIdx.x;
    float logacc = 0.f;     // warp-0 lanes accumulate log(diag)
    float quadneg = 0.f;    // last pivot before sqrt = -u^T S^{-1} u

    for (int p = 0; p < NPAN; p++) {
        int c0 = p * NB;
        // load diag block (L1-bypass; written by other CTAs' SYRK)
        for (int t = tid; t < NB * NB; t += 256) {
            int i = t >> 6, j = t & 63;
            Ld[i][j] = __ldcg(&g_S[(c0 + i) * MP + c0 + j]);
        }
        __syncthreads();

        // --- redundant single-warp diag factorization ---
        if (tid < 32) {
            for (int k = 0; k < NB; k++) {
                float v = Ld[k][k];           // all lanes read (broadcast)
                __syncwarp();
                float s, iv;
                if (p == NPAN - 1 && k == NB - 1) { quadneg = v; s = 1.f; iv = 1.f; }
                else { s = sqrtf(v); iv = 1.f / s; }
                if (tid == 0) { Ld[k][k] = s; dinv[k] = iv; }
                for (int i = k + 1 + tid; i < NB; i += 32) Ld[i][k] *= iv;
                __syncwarp();
                for (int i = k + 1 + tid; i < NB; i += 32) {
                    float lik = Ld[i][k];
                    for (int j = k + 1; j <= i; j++) Ld[i][j] -= lik * Ld[j][k];
                }
                __syncwarp();
            }
            for (int k = tid; k < NB; k += 32)
                if (!(p == NPAN - 1 && k == NB - 1)) logacc += logf(Ld[k][k]);
        }
        __syncthreads();

        // --- TRSM: CTA `rank` handles row panel p+1+rank (if any) ---
        int r = p + 1 + rank;
        if (r < NPAN) {
            int r0 = r * NB;
            for (int t = tid; t < NB * NB; t += 256) {
                int i = t >> 6, j = t & 63;
                B[i][j] = __ldcg(&g_S[(r0 + i) * MP + c0 + j]);
            }
            __syncthreads();
            int row = tid >> 2, part = tid & 3;
            for (int j = 0; j < NB; j++) {
                float s = 0.f;
                for (int c = part; c < j; c += 4) s += B[row][c] * Ld[j][c];
                s += __shfl_down_sync(0xffffffffu, s, 2, 4);
                s += __shfl_down_sync(0xffffffffu, s, 1, 4);
                if (part == 0) B[row][j] = (B[row][j] - s) * dinv[j];
                __syncwarp();
            }
            __syncthreads();
            for (int t = tid; t < NB * NB; t += 256)
                g_S[(r0 + (t >> 6)) * MP + c0 + (t & 63)] = B[t >> 6][t & 63];
            __syncthreads();
        }
        __threadfence();
        CLUSTER_SYNC();

        // --- SYRK trailing update, tiles distributed over cluster ---
        int T = NPAN - 1 - p;
        int ntiles = T * (T + 1) / 2;
        for (int t0 = rank; t0 < ntiles; t0 += CL) {
            int idx = t0, bi = 0;
            while (idx >= bi + 1) { idx -= bi + 1; bi++; }
            int bj = idx;
            int rI = (p + 1 + bi) * NB, rJ = (p + 1 + bj) * NB;
            for (int t = tid; t < NB * NB; t += 256) {
                int i = t >> 6, k = t & 63;
                Ld[i][k] = __ldcg(&g_S[(rI + i) * MP + c0 + k]);
            }
            if (bi != bj) {
                for (int t = tid; t < NB * NB; t += 256) {
                    int i = t >> 6, k = t & 63;
                    B[i][k] = __ldcg(&g_S[(rJ + i) * MP + c0 + k]);
                }
            }
            __syncthreads();
            float (*Lj)[NB + 1] = (bi == bj) ? Ld : B;
            int tx = tid & 15, ty = tid >> 4;
            float acc[4][4] = {};
            for (int k = 0; k < NB; k++) {
                float a[4], b[4];
                #pragma unroll
                for (int u = 0; u < 4; u++) a[u] = Ld[ty * 4 + u][k];
                #pragma unroll
                for (int v = 0; v < 4; v++) b[v] = Lj[tx * 4 + v][k];
                #pragma unroll
                for (int u = 0; u < 4; u++)
                    #pragma unroll
                    for (int v = 0; v < 4; v++) acc[u][v] += a[u] * b[v];
            }
            #pragma unroll
            for (int u = 0; u < 4; u++)
                #pragma unroll
                for (int v = 0; v < 4; v++) {
                    float* ptr = &g_S[(rI + ty * 4 + u) * MP + rJ + tx * 4 + v];
                    *ptr = __ldcg(ptr) - acc[u][v];
                }
            __syncthreads();
        }
        __threadfence();
        CLUSTER_SYNC();
    }

    // --- epilogue: loss (rank 0, warp 0) ---
    if (rank == 0 && tid < 32) {
        float l = logacc;
        #pragma unroll
        for (int o = 16; o; o >>= 1) l += __shfl_down_sync(0xffffffffu, l, o);
        if (tid == 0) {
            double quad1 = -(double)quadneg;
            double e = (double)sig2e[0];
            double logdetV = (double)(n - (NQ0 + NQ1)) * log(e) + g_ldD0 + 2.0 * (double)l;
            double quad = (g_rTr - g_q0 - quad1) / e;
            double loss = 0.5 * (double)n * 1.8378770664093454836
                        + 0.5 * logdetV + 0.5 * quad;
            out[0] = (float)loss;
        }
    }
}

// ---------------- host launcher ----------------
extern "C" void kernel_launch(void* const* d_in, const int* in_sizes, int n_in,
                              void* d_out, int out_size) {
    const float* y_true = (const float*)d_in[0];
    const float* y_pred = (const float*)d_in[1];
    const void*  z0     = d_in[2];
    const void*  z1     = d_in[3];
    const float* sig2e  = (const float*)d_in[4];
    const float* sig2bs = (const float*)d_in[5];
    float* out = (float*)d_out;
    int n = in_sizes[0];

    k_zero<<<256, 256>>>();
    k_fuse<<<1, 1024>>>(y_true, y_pred, z0, z1, sig2e, sig2bs, n);
    k_chol<<<CL, 256>>>(sig2e, out, n);
}

// round 5
// speedup vs baseline: 1.9983x; 1.9983x over previous
#include <cuda_runtime.h>
#include <math.h>

#define NQ0 1000
#define NQ1 500
#define MP  512          // padded+bordered Schur dim: 500 S + 11 identity + 1 border(u)
#define G0P 1024
#define NB  64
#define NPAN (MP/NB)     // 8
#define CL  8            // cluster size
#define NMAX 8192
#define UROW (MP-1)      // 511: border row holding u

// ---------------- device scratch ----------------
static __device__ float g_S[MP*MP];
static __device__ float g_n0[G0P], g_s0[G0P], g_w0[G0P], g_ws0[G0P];
static __device__ float g_n1[MP],  g_s1[MP];
static __device__ int   g_off[G0P+1];
static __device__ int   g_cur[G0P];
static __device__ unsigned short g_csr[NMAX];
static __device__ int   g_i0[NMAX], g_i1[NMAX];
static __device__ double g_rTr, g_ldD0, g_q0;

#define CLUSTER_SYNC() do { \
    asm volatile("barrier.cluster.arrive.aligned;" ::: "memory"); \
    asm volatile("barrier.cluster.wait.aligned;"   ::: "memory"); } while (0)

// ---------------- K1: fused zero/scatter/prep/scan/csr/pairs (1 block) -----
__global__ __launch_bounds__(1024) void k_fuse(
        const float* __restrict__ yt, const float* __restrict__ yp,
        const void* z0, const void* z1,
        const float* __restrict__ sig2e, const float* __restrict__ sig2bs, int n) {
    __shared__ int sm[G0P];
    __shared__ int s_is64;
    __shared__ double sred[3][32];
    int tid = threadIdx.x;

    // --- zero scratch (g_S 1MB via float4, small arrays) ---
    {
        float4* S4 = (float4*)g_S;
        const float4 z4 = make_float4(0.f, 0.f, 0.f, 0.f);
        #pragma unroll 4
        for (int t = tid; t < (MP*MP)/4; t += 1024) S4[t] = z4;
        if (tid < G0P) { g_n0[tid] = 0.f; g_s0[tid] = 0.f; g_cur[tid] = 0; }
        if (tid < MP)  { g_n1[tid] = 0.f; g_s1[tid] = 0.f; }
    }

    // detect int64 vs int32 indices: check odd 32-bit words (high halves)
    if (tid < 32) {
        const unsigned int* w = (const unsigned int*)z0;
        unsigned int v = w[1 + 2*tid] | w[65 + 2*tid];
        unsigned int nz = __ballot_sync(0xffffffffu, v != 0u);
        if (tid == 0) s_is64 = (nz == 0u);
    }
    __syncthreads();
    int is64 = s_is64;

    // --- scatter: counts, group sums, rTr ---
    double rtr = 0.0;
    for (int i = tid; i < n && i < NMAX; i += 1024) {
        float r = yt[i] - yp[i];
        int a, b;
        if (is64) { a = (int)((const long long*)z0)[i]; b = (int)((const long long*)z1)[i]; }
        else      { a = ((const int*)z0)[i];            b = ((const int*)z1)[i]; }
        if ((unsigned)a < (unsigned)NQ0 && (unsigned)b < (unsigned)NQ1) {
            g_i0[i] = a; g_i1[i] = b;
            atomicAdd(&g_n0[a], 1.f); atomicAdd(&g_s0[a], r);
            atomicAdd(&g_n1[b], 1.f); atomicAdd(&g_s1[b], r);
            rtr += (double)r * (double)r;
        } else { g_i0[i] = 0; g_i1[i] = 0; }
    }
    __syncthreads();

    // --- prep: w0, logdet(D0), q0, S diag + u (border row) base ---
    float e = sig2e[0], b0 = sig2bs[0], b1 = sig2bs[1];
    float sqb1 = sqrtf(b1);
    double ld = 0.0, q = 0.0;
    for (int i = tid; i < G0P + MP; i += 1024) {
        if (i < G0P) {
            float d0 = e + b0 * g_n0[i];
            float w  = 1.f / d0;
            g_w0[i] = w; g_ws0[i] = g_s0[i] * w;
            if (i < NQ0) {
                ld += log((double)d0);
                q  += (double)b0 * (double)g_s0[i] * (double)g_s0[i] * (double)w;
            }
        } else {
            int j = i - G0P;
            if (j < NQ1) {
                g_S[j*MP + j] = e + b1 * g_n1[j];
                g_S[UROW*MP + j] = sqb1 * g_s1[j];      // border row = u
            } else if (j < UROW) {
                g_S[j*MP + j] = 1.f;                    // identity padding
            }                                           // S[511][511] stays 0
        }
    }
    __syncthreads();

    // --- scan over group-0 counts ---
    sm[tid] = (int)g_n0[tid];
    __syncthreads();
    for (int d = 1; d < G0P; d <<= 1) {
        int v = (tid >= d) ? sm[tid - d] : 0;
        __syncthreads();
        sm[tid] += v;
        __syncthreads();
    }
    g_off[tid + 1] = sm[tid];
    if (tid == 0) g_off[0] = 0;
    __syncthreads();

    // --- csr build + u correction ---
    float ucoef = -sqb1 * b0;
    for (int i = tid; i < n && i < NMAX; i += 1024) {
        int a = g_i0[i], b = g_i1[i];
        int p = atomicAdd(&g_cur[a], 1);
        g_csr[g_off[a] + p] = (unsigned short)b;
        atomicAdd(&g_S[UROW*MP + b], ucoef * g_ws0[a]);
    }
    __syncthreads();

    // --- pairs: S -= b0*b1 * C^T D0^{-1} C (sparse all-pairs per group) ---
    int wid = tid >> 5, lane = tid & 31;
    for (int g = wid; g < NQ0; g += 32) {
        int lo = g_off[g], len = g_off[g + 1] - lo;
        if (!len) continue;
        float coef = -b0 * b1 * g_w0[g];
        int tot = len * len;
        for (int t = lane; t < tot; t += 32) {
            int a = g_csr[lo + t / len];
            int b = g_csr[lo + t % len];
            atomicAdd(&g_S[a * MP + b], coef);
        }
    }

    // --- reduce rtr, ld, q -> globals ---
    #pragma unroll
    for (int o = 16; o; o >>= 1) {
        rtr += __shfl_down_sync(0xffffffffu, rtr, o);
        ld  += __shfl_down_sync(0xffffffffu, ld,  o);
        q   += __shfl_down_sync(0xffffffffu, q,   o);
    }
    if (lane == 0) { sred[0][wid] = rtr; sred[1][wid] = ld; sred[2][wid] = q; }
    __syncthreads();
    if (tid == 0) {
        double a0 = 0, a1 = 0, a2 = 0;
        for (int k = 0; k < 32; k++) { a0 += sred[0][k]; a1 += sred[1][k]; a2 += sred[2][k]; }
        g_rTr = a0; g_ldD0 = a1; g_q0 = a2;
    }
}

// ---------------- K2: clustered Cholesky (deferred scaling) + loss ----------
__global__ void __cluster_dims__(CL,1,1) __launch_bounds__(256,1)
k_chol(const float* __restrict__ sig2e, float* __restrict__ out, int n) {
    __shared__ float Ld[NB][NB + 1];
    __shared__ float B [NB][NB + 1];
    __shared__ float dinv[NB];
    __shared__ float s_quad;
    int rank = blockIdx.x;
    int tid = threadIdx.x;
    int ty = tid >> 5, tx = tid & 31;
    float logsum = 0.f;   // per-thread (tid<64): sum of log(d_k) = log pivots BEFORE sqrt

    for (int p = 0; p < NPAN; p++) {
        int c0 = p * NB;
        // load diag block (L1-bypass: written by other CTAs' SYRK)
        for (int t = tid; t < NB * NB; t += 256) {
            int i = t >> 6, j = t & 63;
            Ld[i][j] = __ldcg(&g_S[(c0 + i) * MP + c0 + j]);
        }
        __syncthreads();

        // --- deferred-scaling factorization: 1 barrier per pivot step ---
        #pragma unroll 1
        for (int k = 0; k < NB; k++) {
            float v = Ld[k][k];
            float iv2 = __frcp_rn(v);
            int j0 = k + 1 + tx, j1 = j0 + 32;
            float c0v = (j0 < NB) ? Ld[j0][k] * iv2 : 0.f;
            float c1v = (j1 < NB) ? Ld[j1][k] * iv2 : 0.f;
            for (int i = k + 1 + ty; i < NB; i += 8) {
                float lik = Ld[i][k];
                if (j0 <= i) Ld[i][j0] -= lik * c0v;
                if (j1 <= i) Ld[i][j1] -= lik * c1v;
            }
            __syncthreads();
        }

        // --- scaling: pivots -> dinv/log; scale strictly-lower columns ---
        if (tid < NB) {
            float v = Ld[tid][tid];
            int border = (p == NPAN - 1) && (tid == NB - 1);
            if (border) { s_quad = v; dinv[tid] = 1.f; }
            else        { dinv[tid] = rsqrtf(v); logsum += logf(v); }  // log d_k
        }
        __syncthreads();
        for (int t = tid; t < NB * NB; t += 256) {
            int i = t >> 6, j = t & 63;
            if (i > j) Ld[i][j] *= dinv[j];
        }
        __syncthreads();

        // --- TRSM: CTA `rank` handles row panel p+1+rank (one thread/row) ---
        int r = p + 1 + rank;
        if (r < NPAN) {
            int r0 = r * NB;
            for (int t = tid; t < NB * NB; t += 256) {
                int i = t >> 6, j = t & 63;
                B[i][j] = __ldcg(&g_S[(r0 + i) * MP + c0 + j]);
            }
            __syncthreads();
            if (tid < NB) {
                int row = tid;
                for (int j = 0; j < NB; j++) {
                    float a = B[row][j];
                    float p0 = 0, p1 = 0, p2 = 0, p3 = 0;
                    int c = 0;
                    for (; c + 4 <= j; c += 4) {
                        p0 += B[row][c]     * Ld[j][c];
                        p1 += B[row][c + 1] * Ld[j][c + 1];
                        p2 += B[row][c + 2] * Ld[j][c + 2];
                        p3 += B[row][c + 3] * Ld[j][c + 3];
                    }
                    for (; c < j; c++) p0 += B[row][c] * Ld[j][c];
                    B[row][j] = (a - ((p0 + p1) + (p2 + p3))) * dinv[j];
                }
            }
            __syncthreads();
            for (int t = tid; t < NB * NB; t += 256)
                g_S[(r0 + (t >> 6)) * MP + c0 + (t & 63)] = B[t >> 6][t & 63];
        }
        __threadfence();
        CLUSTER_SYNC();

        // --- SYRK trailing update, tiles distributed over cluster ---
        int T = NPAN - 1 - p;
        int ntiles = T * (T + 1) / 2;
        for (int t0 = rank; t0 < ntiles; t0 += CL) {
            int idx = t0, bi = 0;
            while (idx >= bi + 1) { idx -= bi + 1; bi++; }
            int bj = idx;
            int rI = (p + 1 + bi) * NB, rJ = (p + 1 + bj) * NB;
            for (int t = tid; t < NB * NB; t += 256) {
                int i = t >> 6, k = t & 63;
                Ld[i][k] = __ldcg(&g_S[(rI + i) * MP + c0 + k]);
            }
            if (bi != bj) {
                for (int t = tid; t < NB * NB; t += 256) {
                    int i = t >> 6, k = t & 63;
                    B[i][k] = __ldcg(&g_S[(rJ + i) * MP + c0 + k]);
                }
            }
            __syncthreads();
            float (*Lj)[NB + 1] = (bi == bj) ? Ld : B;
            int sx = tid & 15, sy = tid >> 4;
            float acc[4][4] = {};
            for (int k = 0; k < NB; k++) {
                float a[4], b[4];
                #pragma unroll
                for (int u = 0; u < 4; u++) a[u] = Ld[sy * 4 + u][k];
                #pragma unroll
                for (int v = 0; v < 4; v++) b[v] = Lj[sx * 4 + v][k];
                #pragma unroll
                for (int u = 0; u < 4; u++)
                    #pragma unroll
                    for (int v = 0; v < 4; v++) acc[u][v] += a[u] * b[v];
            }
            #pragma unroll
            for (int u = 0; u < 4; u++)
                #pragma unroll
                for (int v = 0; v < 4; v++) {
                    float* ptr = &g_S[(rI + sy * 4 + u) * MP + rJ + sx * 4 + v];
                    *ptr = __ldcg(ptr) - acc[u][v];
                }
            __syncthreads();
        }
        __threadfence();
        CLUSTER_SYNC();
    }

    // --- epilogue: reduce logdet (register accumulators), emit loss --------
    if (rank == 0) {
        if (tid < NB) dinv[tid] = logsum;   // reuse dinv as reduction buffer
        __syncthreads();
        if (tid == 0) {
            float l = 0.f;
            for (int k = 0; k < NB; k++) l += dinv[k];   // l = sum log d_k = logdet S
            double quad1 = -(double)s_quad;
            double e = (double)sig2e[0];
            double logdetV = (double)(n - (NQ0 + NQ1)) * log(e) + g_ldD0 + (double)l;
            double quad = (g_rTr - g_q0 - quad1) / e;
            double loss = 0.5 * (double)n * 1.8378770664093454836
                        + 0.5 * logdetV + 0.5 * quad;
            out[0] = (float)loss;
        }
    }
}

// ---------------- host launcher ----------------
extern "C" void kernel_launch(void* const* d_in, const int* in_sizes, int n_in,
                              void* d_out, int out_size) {
    const float* y_true = (const float*)d_in[0];
    const float* y_pred = (const float*)d_in[1];
    const void*  z0     = d_in[2];
    const void*  z1     = d_in[3];
    const float* sig2e  = (const float*)d_in[4];
    const float* sig2bs = (const float*)d_in[5];
    float* out = (float*)d_out;
    int n = in_sizes[0];

    k_fuse<<<1, 1024>>>(y_true, y_pred, z0, z1, sig2e, sig2bs, n);
    k_chol<<<CL, 256>>>(sig2e, out, n);
}

// round 6
// speedup vs baseline: 3.4701x; 1.7365x over previous
#include <cuda_runtime.h>
#include <math.h>

#define NQ0 1000
#define NQ1 500
#define MP  512          // padded+bordered Schur dim: 500 S + 11 identity + 1 border(u)
#define G0P 1024
#define NB  64
#define NPAN (MP/NB)     // 8
#define CL  8            // cluster size
#define NT  256          // threads per CTA
#define GT  (CL*NT)      // 2048 cluster-wide threads
#define NMAX 8192
#define UROW (MP-1)      // 511: border row holding u

// ---------------- device scratch ----------------
static __device__ float g_S[MP*MP];
static __device__ float g_n0[G0P], g_s0[G0P], g_w0[G0P], g_ws0[G0P];
static __device__ float g_n1[MP],  g_s1[MP];
static __device__ int   g_off[G0P+1];
static __device__ int   g_cur[G0P];
static __device__ unsigned short g_csr[NMAX];
static __device__ int   g_i0[NMAX], g_i1[NMAX];
static __device__ double g_rTr, g_ldD0, g_q0;

#define CLUSTER_SYNC() do { \
    asm volatile("barrier.cluster.arrive.aligned;" ::: "memory"); \
    asm volatile("barrier.cluster.wait.aligned;"   ::: "memory"); } while (0)

// =================== single fused cluster kernel ===========================
__global__ void __cluster_dims__(CL,1,1) __launch_bounds__(NT,1)
k_all(const float* __restrict__ yt, const float* __restrict__ yp,
      const void* z0, const void* z1,
      const float* __restrict__ sig2e, const float* __restrict__ sig2bs,
      float* __restrict__ out, int n)
{
    __shared__ float Ld[NB][NB+1];
    __shared__ float Bs[NB][NB+1];
    __shared__ float colbuf[NB][NB/2+1];
    __shared__ float dinv[NB];
    __shared__ float s_quad;
    __shared__ double sred[3][8];
    __shared__ int   wsum[8];
    __shared__ int   s_is64;

    int rank = blockIdx.x;
    int tid  = threadIdx.x;
    int lane = tid & 31, wid = tid >> 5;
    int gt   = rank * NT + tid;

    // ---------------- A: zero scratch + detect index width -----------------
    {
        float4* S4 = (float4*)g_S;
        const float4 z4 = make_float4(0.f,0.f,0.f,0.f);
        for (int i = gt; i < (MP*MP)/4; i += GT) S4[i] = z4;
        if (gt < G0P) { g_n0[gt]=0.f; g_s0[gt]=0.f; g_cur[gt]=0; }
        if (gt < MP)  { g_n1[gt]=0.f; g_s1[gt]=0.f; }
        if (gt == 0)  { g_rTr=0.0; g_ldD0=0.0; g_q0=0.0; g_off[0]=0; }
        if (wid == 0) {
            const unsigned int* w = (const unsigned int*)z0;
            unsigned int v = w[1+2*lane] | w[65+2*lane];
            unsigned int nz = __ballot_sync(0xffffffffu, v != 0u);
            if (lane == 0) s_is64 = (nz == 0u);
        }
    }
    __threadfence(); CLUSTER_SYNC();
    int is64 = s_is64;

    // ---------------- B: scatter (counts, sums, rTr) -----------------------
    double rtr = 0.0;
    for (int i = gt; i < n && i < NMAX; i += GT) {
        float r = yt[i] - yp[i];
        int a, b;
        if (is64) { a=(int)((const long long*)z0)[i]; b=(int)((const long long*)z1)[i]; }
        else      { a=((const int*)z0)[i];            b=((const int*)z1)[i]; }
        if ((unsigned)a < (unsigned)NQ0 && (unsigned)b < (unsigned)NQ1) {
            g_i0[i]=a; g_i1[i]=b;
            atomicAdd(&g_n0[a],1.f); atomicAdd(&g_s0[a],r);
            atomicAdd(&g_n1[b],1.f); atomicAdd(&g_s1[b],r);
            rtr += (double)r * (double)r;
        } else { g_i0[i]=0; g_i1[i]=0; }
    }
    #pragma unroll
    for (int o=16;o;o>>=1) rtr += __shfl_down_sync(0xffffffffu, rtr, o);
    if (lane==0) sred[0][wid] = rtr;
    __syncthreads();
    if (tid==0){ double s=0; for (int k2=0;k2<8;k2++) s+=sred[0][k2]; atomicAdd(&g_rTr,s); }
    __threadfence(); CLUSTER_SYNC();

    // ---------------- C: prep + prefix scan (rank 0) -----------------------
    float e = sig2e[0], b0 = sig2bs[0], b1 = sig2bs[1];
    float sqb1 = sqrtf(b1);
    {
        double ld = 0.0, q = 0.0;
        for (int i = gt; i < G0P + MP; i += GT) {
            if (i < G0P) {
                float cnt = __ldcg(&g_n0[i]);
                float s0v = __ldcg(&g_s0[i]);
                float d0 = e + b0*cnt, w = 1.f/d0;
                g_w0[i] = w; g_ws0[i] = s0v*w;
                if (i < NQ0) {
                    ld += log((double)d0);
                    q  += (double)b0*(double)s0v*(double)s0v*(double)w;
                }
            } else {
                int j = i - G0P;
                if (j < NQ1) {
                    g_S[j*MP+j] = e + b1*__ldcg(&g_n1[j]);
                    g_S[UROW*MP+j] = sqb1*__ldcg(&g_s1[j]);   // border row = u
                } else if (j < UROW) g_S[j*MP+j] = 1.f;       // identity padding
            }
        }
        #pragma unroll
        for (int o=16;o;o>>=1) {
            ld += __shfl_down_sync(0xffffffffu, ld, o);
            q  += __shfl_down_sync(0xffffffffu, q,  o);
        }
        if (lane==0) { sred[1][wid]=ld; sred[2][wid]=q; }
        __syncthreads();
        if (tid==0) {
            double a1=0,a2=0;
            for (int k2=0;k2<8;k2++){a1+=sred[1][k2];a2+=sred[2][k2];}
            atomicAdd(&g_ldD0,a1); atomicAdd(&g_q0,a2);
        }
    }
    if (rank == 0) {   // scan: 256 threads x 4 elements
        int base = tid*4;
        int c0i=(int)__ldcg(&g_n0[base]),   c1i=(int)__ldcg(&g_n0[base+1]);
        int c2i=(int)__ldcg(&g_n0[base+2]), c3i=(int)__ldcg(&g_n0[base+3]);
        int s = c0i+c1i+c2i+c3i;
        int v = s;
        #pragma unroll
        for (int o=1;o<32;o<<=1){int y=__shfl_up_sync(0xffffffffu,v,o); if(lane>=o)v+=y;}
        if (lane==31) wsum[wid]=v;
        __syncthreads();
        if (wid==0 && lane<8){
            int wv=wsum[lane];
            #pragma unroll
            for (int o=1;o<8;o<<=1){int y=__shfl_up_sync(0xffu,wv,o); if(lane>=o)wv+=y;}
            wsum[lane]=wv;
        }
        __syncthreads();
        int excl = v - s + (wid ? wsum[wid-1] : 0);
        g_off[base+1]=excl+c0i;
        g_off[base+2]=excl+c0i+c1i;
        g_off[base+3]=excl+c0i+c1i+c2i;
        g_off[base+4]=excl+s;
    }
    __threadfence(); CLUSTER_SYNC();

    // ---------------- D: csr build + u correction --------------------------
    {
        float ucoef = -sqb1 * b0;
        for (int i = gt; i < n && i < NMAX; i += GT) {
            int a = g_i0[i], b = g_i1[i];
            int ppos = atomicAdd(&g_cur[a], 1);
            g_csr[__ldcg(&g_off[a]) + ppos] = (unsigned short)b;
            atomicAdd(&g_S[UROW*MP + b], ucoef * __ldcg(&g_ws0[a]));
        }
    }
    __threadfence(); CLUSTER_SYNC();

    // ---------------- E: pairs (sparse C^T D0^{-1} C) ----------------------
    {
        int gw = rank*8 + wid;
        for (int g = gw; g < NQ0; g += CL*8) {
            int lo  = __ldcg(&g_off[g]);
            int len = __ldcg(&g_off[g+1]) - lo;
            if (!len) continue;
            float coef = -b0*b1*__ldcg(&g_w0[g]);
            int tot = len*len;
            for (int t2 = lane; t2 < tot; t2 += 32) {
                int a = (int)__ldcg(&g_csr[lo + t2/len]);
                int b = (int)__ldcg(&g_csr[lo + t2%len]);
                atomicAdd(&g_S[a*MP + b], coef);
            }
        }
    }
    __threadfence(); CLUSTER_SYNC();

    // ---------------- F: bordered blocked Cholesky -------------------------
    float logsum = 0.f;   // tid<64: per-diag-slot sum of log(pivot)
    int tx = lane, ty = wid;

    for (int p = 0; p < NPAN; p++) {
        int c0 = p*NB;
        // load diag block (float4, L1-bypass)
        for (int t2 = tid; t2 < NB*16; t2 += NT) {
            int i = t2 >> 4, j4 = (t2 & 15) << 2;
            float4 v = __ldcg((const float4*)&g_S[(c0+i)*MP + c0 + j4]);
            Ld[i][j4]=v.x; Ld[i][j4+1]=v.y; Ld[i][j4+2]=v.z; Ld[i][j4+3]=v.w;
        }
        __syncthreads();

        // --- batched (rank-2) deferred-scaling factorization ---
        // batch (k,k+1): reads ONLY columns k,k+1 of Ld; writes columns >=k+2
        // and colbuf (final column k+1). No read/write overlap -> 1 barrier.
        #pragma unroll 1
        for (int b = 0; b < NB/2; b++) {
            int k = 2*b;
            float dk  = Ld[k][k];
            float ivk = __frcp_rn(dk);
            float tco = Ld[k+1][k]*ivk;
            float dk1 = Ld[k+1][k+1] - Ld[k+1][k]*tco;
            float ivk1= __frcp_rn(dk1);
            int j0 = k+2+tx, j1 = j0+32;
            float c0v=0.f, e0v=0.f, c1v=0.f, e1v=0.f;
            if (j0 < NB){ float a=Ld[j0][k]; float ap=Ld[j0][k+1]-a*tco; c0v=a*ivk; e0v=ap*ivk1; }
            if (j1 < NB){ float a=Ld[j1][k]; float ap=Ld[j1][k+1]-a*tco; c1v=a*ivk; e1v=ap*ivk1; }
            for (int i = k+1+ty; i < NB; i += 8) {
                float aik = Ld[i][k], aik1 = Ld[i][k+1];
                float api = aik1 - aik*tco;
                if (tx == 0) colbuf[i][b] = api;
                if (j0 <= i) Ld[i][j0] -= aik*c0v + api*e0v;
                if (j1 <= i) Ld[i][j1] -= aik*c1v + api*e1v;
            }
            __syncthreads();
        }
        // restore odd columns (final values) from colbuf
        for (int t2 = tid; t2 < NB*(NB/2); t2 += NT) {
            int i = t2 >> 5, b = t2 & 31;
            int j = 2*b+1;
            if (i >= j) Ld[i][j] = colbuf[i][b];
        }
        __syncthreads();
        // scaling: pivots -> dinv/log; scale strictly-lower columns
        if (tid < NB) {
            float v = Ld[tid][tid];
            if (p == NPAN-1 && tid == NB-1) { s_quad = v; dinv[tid] = 1.f; }
            else { dinv[tid] = rsqrtf(v); logsum += logf(v); }   // log d_k
        }
        __syncthreads();
        for (int t2 = tid; t2 < NB*NB; t2 += NT) {
            int i = t2 >> 6, j = t2 & 63;
            if (i > j) Ld[i][j] *= dinv[j];
        }
        __syncthreads();

        // --- blocked right-looking TRSM: CTA `rank` owns row panel p+1+rank
        int r = p + 1 + rank;
        if (r < NPAN) {
            int r0 = r*NB;
            for (int t2 = tid; t2 < NB*16; t2 += NT) {
                int i = t2 >> 4, j4 = (t2 & 15) << 2;
                float4 v = __ldcg((const float4*)&g_S[(r0+i)*MP + c0 + j4]);
                Bs[i][j4]=v.x; Bs[i][j4+1]=v.y; Bs[i][j4+2]=v.z; Bs[i][j4+3]=v.w;
            }
            __syncthreads();
            int row = tid & 63, qq = tid >> 6;
            #pragma unroll 1
            for (int blk = 0; blk < 8; blk++) {
                int cb = blk*8;
                if (tid < NB) {   // serial solve within 8-column block
                    #pragma unroll
                    for (int jj = 0; jj < 8; jj++) {
                        int j = cb + jj;
                        float a = Bs[tid][j];
                        for (int c = cb; c < j; c++) a -= Bs[tid][c]*Ld[j][c];
                        Bs[tid][j] = a * dinv[j];
                    }
                }
                __syncthreads();
                if (blk < 7) {    // parallel update of later columns
                    float rb[8];
                    #pragma unroll
                    for (int c = 0; c < 8; c++) rb[c] = Bs[row][cb+c];
                    for (int j = cb+8+qq; j < NB; j += 4) {
                        float s = 0.f;
                        #pragma unroll
                        for (int c = 0; c < 8; c++) s += rb[c]*Ld[j][cb+c];
                        Bs[row][j] -= s;
                    }
                    __syncthreads();
                }
            }
            for (int t2 = tid; t2 < NB*16; t2 += NT) {
                int i = t2 >> 4, j4 = (t2 & 15) << 2;
                float4 v = make_float4(Bs[i][j4],Bs[i][j4+1],Bs[i][j4+2],Bs[i][j4+3]);
                *(float4*)&g_S[(r0+i)*MP + c0 + j4] = v;
            }
        }

        if (p < NPAN-1) {
            __threadfence(); CLUSTER_SYNC();
            // --- SYRK trailing update, tiles distributed over cluster ---
            int T = NPAN-1-p;
            int ntiles = T*(T+1)/2;
            for (int t0 = rank; t0 < ntiles; t0 += CL) {
                int idx = t0, bi = 0;
                while (idx >= bi+1){ idx -= bi+1; bi++; }
                int bj = idx;
                int rI = (p+1+bi)*NB, rJ = (p+1+bj)*NB;
                for (int t2 = tid; t2 < NB*16; t2 += NT) {
                    int i = t2 >> 4, j4 = (t2 & 15) << 2;
                    float4 v = __ldcg((const float4*)&g_S[(rI+i)*MP + c0 + j4]);
                    Ld[i][j4]=v.x; Ld[i][j4+1]=v.y; Ld[i][j4+2]=v.z; Ld[i][j4+3]=v.w;
                }
                if (bi != bj) {
                    for (int t2 = tid; t2 < NB*16; t2 += NT) {
                        int i = t2 >> 4, j4 = (t2 & 15) << 2;
                        float4 v = __ldcg((const float4*)&g_S[(rJ+i)*MP + c0 + j4]);
                        Bs[i][j4]=v.x; Bs[i][j4+1]=v.y; Bs[i][j4+2]=v.z; Bs[i][j4+3]=v.w;
                    }
                }
                __syncthreads();
                float (*Lj)[NB+1] = (bi==bj) ? Ld : Bs;
                int sx = tid & 15, sy = tid >> 4;
                float acc[4][4] = {};
                #pragma unroll 4
                for (int kk = 0; kk < NB; kk++) {
                    float av[4], bv[4];
                    #pragma unroll
                    for (int u=0;u<4;u++) av[u]=Ld[sy*4+u][kk];
                    #pragma unroll
                    for (int v2=0;v2<4;v2++) bv[v2]=Lj[sx*4+v2][kk];
                    #pragma unroll
                    for (int u=0;u<4;u++)
                        #pragma unroll
                        for (int v2=0;v2<4;v2++) acc[u][v2] += av[u]*bv[v2];
                }
                #pragma unroll
                for (int u=0;u<4;u++) {
                    float* ptr = &g_S[(rI+sy*4+u)*MP + rJ + sx*4];
                    float4 old = __ldcg((const float4*)ptr);
                    old.x -= acc[u][0]; old.y -= acc[u][1];
                    old.z -= acc[u][2]; old.w -= acc[u][3];
                    *(float4*)ptr = old;
                }
                __syncthreads();
            }
            __threadfence(); CLUSTER_SYNC();
        }
    }

    // ---------------- epilogue: loss (rank 0) ------------------------------
    if (rank == 0) {
        if (tid < NB) dinv[tid] = logsum;
        __syncthreads();
        if (tid == 0) {
            float l = 0.f;
            for (int k2 = 0; k2 < NB; k2++) l += dinv[k2];   // logdet S
            double quad1 = -(double)s_quad;
            double ed = (double)e;
            double rTrv = __ldcg(&g_rTr);
            double ldD0v = __ldcg(&g_ldD0);
            double q0v  = __ldcg(&g_q0);
            double logdetV = (double)(n - (NQ0 + NQ1)) * log(ed) + ldD0v + (double)l;
            double quad = (rTrv - q0v - quad1) / ed;
            double loss = 0.5 * (double)n * 1.8378770664093454836
                        + 0.5 * logdetV + 0.5 * quad;
            out[0] = (float)loss;
        }
    }
}

// ---------------- host launcher --------------------------------------------
extern "C" void kernel_launch(void* const* d_in, const int* in_sizes, int n_in,
                              void* d_out, int out_size) {
    const float* y_true = (const float*)d_in[0];
    const float* y_pred = (const float*)d_in[1];
    const void*  z0     = d_in[2];
    const void*  z1     = d_in[3];
    const float* sig2e  = (const float*)d_in[4];
    const float* sig2bs = (const float*)d_in[5];
    float* out = (float*)d_out;
    int n = in_sizes[0];

    k_all<<<CL, NT>>>(y_true, y_pred, z0, z1, sig2e, sig2bs, out, n);
}

// round 7
// speedup vs baseline: 3.6584x; 1.0543x over previous
#include <cuda_runtime.h>
#include <math.h>

#define NQ0 1000
#define NQ1 500
#define MP  512          // padded+bordered Schur dim: 500 S + 11 identity + 1 border(u)
#define G0P 1024
#define NB  64
#define NPAN (MP/NB)     // 8
#define CL  8            // cluster size
#define NT  512          // threads per CTA (16 warps)
#define GT  (CL*NT)      // 4096 cluster-wide threads
#define NMAX 8192
#define UROW (MP-1)      // 511: border row holding u

// ---------------- device scratch ----------------
static __device__ float g_S[MP*MP];
static __device__ float g_n0[G0P], g_s0[G0P], g_w0[G0P], g_ws0[G0P];
static __device__ float g_n1[MP],  g_s1[MP];
static __device__ int   g_off[G0P+1];
static __device__ int   g_cur[G0P];
static __device__ unsigned short g_csr[NMAX];
static __device__ int   g_i0[NMAX], g_i1[NMAX];
static __device__ double g_rTr, g_ldD0, g_q0;

#define CLUSTER_SYNC() do { \
    asm volatile("barrier.cluster.arrive.aligned;" ::: "memory"); \
    asm volatile("barrier.cluster.wait.aligned;"   ::: "memory"); } while (0)

// =================== single fused cluster kernel ===========================
__global__ void __cluster_dims__(CL,1,1) __launch_bounds__(NT,1)
k_all(const float* __restrict__ yt, const float* __restrict__ yp,
      const void* z0, const void* z1,
      const float* __restrict__ sig2e, const float* __restrict__ sig2bs,
      float* __restrict__ out, int n)
{
    __shared__ float Ld[NB][NB+1];
    __shared__ float Bs[NB][NB+1];
    __shared__ float colbuf[NB][NB/2+1];
    __shared__ float dinv[NB];
    __shared__ float s_quad;
    __shared__ double sred[3][16];
    __shared__ int   wsum[16];
    __shared__ int   s_is64;

    int rank = blockIdx.x;
    int tid  = threadIdx.x;
    int lane = tid & 31, wid = tid >> 5;
    int gt   = rank * NT + tid;

    // ---------------- A: zero scratch + detect index width -----------------
    {
        float4* S4 = (float4*)g_S;
        const float4 z4 = make_float4(0.f,0.f,0.f,0.f);
        for (int i = gt; i < (MP*MP)/4; i += GT) S4[i] = z4;
        if (gt < G0P) { g_n0[gt]=0.f; g_s0[gt]=0.f; g_cur[gt]=0; }
        if (gt < MP)  { g_n1[gt]=0.f; g_s1[gt]=0.f; }
        if (gt == 0)  { g_rTr=0.0; g_ldD0=0.0; g_q0=0.0; g_off[0]=0; }
        if (wid == 0) {
            const unsigned int* w = (const unsigned int*)z0;
            unsigned int v = w[1+2*lane] | w[65+2*lane];
            unsigned int nz = __ballot_sync(0xffffffffu, v != 0u);
            if (lane == 0) s_is64 = (nz == 0u);
        }
    }
    __threadfence(); CLUSTER_SYNC();
    int is64 = s_is64;

    // ---------------- B: scatter (counts, sums, rTr) -----------------------
    double rtr = 0.0;
    for (int i = gt; i < n && i < NMAX; i += GT) {
        float r = yt[i] - yp[i];
        int a, b;
        if (is64) { a=(int)((const long long*)z0)[i]; b=(int)((const long long*)z1)[i]; }
        else      { a=((const int*)z0)[i];            b=((const int*)z1)[i]; }
        if ((unsigned)a < (unsigned)NQ0 && (unsigned)b < (unsigned)NQ1) {
            g_i0[i]=a; g_i1[i]=b;
            atomicAdd(&g_n0[a],1.f); atomicAdd(&g_s0[a],r);
            atomicAdd(&g_n1[b],1.f); atomicAdd(&g_s1[b],r);
            rtr += (double)r * (double)r;
        } else { g_i0[i]=0; g_i1[i]=0; }
    }
    #pragma unroll
    for (int o=16;o;o>>=1) rtr += __shfl_down_sync(0xffffffffu, rtr, o);
    if (lane==0) sred[0][wid] = rtr;
    __syncthreads();
    if (tid==0){ double s=0; for (int k2=0;k2<16;k2++) s+=sred[0][k2]; atomicAdd(&g_rTr,s); }
    __threadfence(); CLUSTER_SYNC();

    // ---------------- C: prep + prefix scan (rank 0) -----------------------
    float e = sig2e[0], b0 = sig2bs[0], b1 = sig2bs[1];
    float sqb1 = sqrtf(b1);
    {
        double ld = 0.0, q = 0.0;
        for (int i = gt; i < G0P + MP; i += GT) {
            if (i < G0P) {
                float cnt = __ldcg(&g_n0[i]);
                float s0v = __ldcg(&g_s0[i]);
                float d0 = e + b0*cnt, w = 1.f/d0;
                g_w0[i] = w; g_ws0[i] = s0v*w;
                if (i < NQ0) {
                    ld += log((double)d0);
                    q  += (double)b0*(double)s0v*(double)s0v*(double)w;
                }
            } else {
                int j = i - G0P;
                if (j < NQ1) {
                    g_S[j*MP+j] = e + b1*__ldcg(&g_n1[j]);
                    g_S[UROW*MP+j] = sqb1*__ldcg(&g_s1[j]);   // border row = u
                } else if (j < UROW) g_S[j*MP+j] = 1.f;       // identity padding
            }
        }
        #pragma unroll
        for (int o=16;o;o>>=1) {
            ld += __shfl_down_sync(0xffffffffu, ld, o);
            q  += __shfl_down_sync(0xffffffffu, q,  o);
        }
        if (lane==0) { sred[1][wid]=ld; sred[2][wid]=q; }
        __syncthreads();
        if (tid==0) {
            double a1=0,a2=0;
            for (int k2=0;k2<16;k2++){a1+=sred[1][k2];a2+=sred[2][k2];}
            atomicAdd(&g_ldD0,a1); atomicAdd(&g_q0,a2);
        }
    }
    if (rank == 0) {   // scan: 512 threads x 2 elements
        int base = tid*2;
        int c0i=(int)__ldcg(&g_n0[base]), c1i=(int)__ldcg(&g_n0[base+1]);
        int s = c0i+c1i;
        int v = s;
        #pragma unroll
        for (int o=1;o<32;o<<=1){int y=__shfl_up_sync(0xffffffffu,v,o); if(lane>=o)v+=y;}
        if (lane==31) wsum[wid]=v;
        __syncthreads();
        if (wid==0 && lane<16){
            int wv=wsum[lane];
            #pragma unroll
            for (int o=1;o<16;o<<=1){int y=__shfl_up_sync(0xffffu,wv,o); if(lane>=o)wv+=y;}
            wsum[lane]=wv;
        }
        __syncthreads();
        int excl = v - s + (wid ? wsum[wid-1] : 0);
        g_off[base+1]=excl+c0i;
        g_off[base+2]=excl+s;
    }
    __threadfence(); CLUSTER_SYNC();

    // ---------------- D: csr build + u correction --------------------------
    {
        float ucoef = -sqb1 * b0;
        for (int i = gt; i < n && i < NMAX; i += GT) {
            int a = g_i0[i], b = g_i1[i];
            int ppos = atomicAdd(&g_cur[a], 1);
            g_csr[__ldcg(&g_off[a]) + ppos] = (unsigned short)b;
            atomicAdd(&g_S[UROW*MP + b], ucoef * __ldcg(&g_ws0[a]));
        }
    }
    __threadfence(); CLUSTER_SYNC();

    // ---------------- E: pairs (sparse C^T D0^{-1} C) ----------------------
    {
        int gw = rank*16 + wid;
        for (int g = gw; g < NQ0; g += CL*16) {
            int lo  = __ldcg(&g_off[g]);
            int len = __ldcg(&g_off[g+1]) - lo;
            if (!len) continue;
            float coef = -b0*b1*__ldcg(&g_w0[g]);
            int tot = len*len;
            for (int t2 = lane; t2 < tot; t2 += 32) {
                int a = (int)__ldcg(&g_csr[lo + t2/len]);
                int b = (int)__ldcg(&g_csr[lo + t2%len]);
                atomicAdd(&g_S[a*MP + b], coef);
            }
        }
    }
    __threadfence(); CLUSTER_SYNC();

    // ---------------- F: bordered blocked Cholesky -------------------------
    float logsum = 0.f;   // tid<64: per-diag-slot sum of log(pivot)
    int tx = lane, ty = wid;   // fact map: 16 row-streams x 32 col-lanes

    for (int p = 0; p < NPAN; p++) {
        int c0 = p*NB;
        // load diag block (float4, L1-bypass)
        for (int t2 = tid; t2 < NB*16; t2 += NT) {
            int i = t2 >> 4, j4 = (t2 & 15) << 2;
            float4 v = __ldcg((const float4*)&g_S[(c0+i)*MP + c0 + j4]);
            Ld[i][j4]=v.x; Ld[i][j4+1]=v.y; Ld[i][j4+2]=v.z; Ld[i][j4+3]=v.w;
        }
        __syncthreads();

        // --- batched (rank-2) deferred-scaling factorization ---
        #pragma unroll 1
        for (int b = 0; b < NB/2; b++) {
            int k = 2*b;
            float dk  = Ld[k][k];
            float ivk = __frcp_rn(dk);
            float tco = Ld[k+1][k]*ivk;
            float dk1 = Ld[k+1][k+1] - Ld[k+1][k]*tco;
            float ivk1= __frcp_rn(dk1);
            int j0 = k+2+tx, j1 = j0+32;
            float c0v=0.f, e0v=0.f, c1v=0.f, e1v=0.f;
            if (j0 < NB){ float a=Ld[j0][k]; float ap=Ld[j0][k+1]-a*tco; c0v=a*ivk; e0v=ap*ivk1; }
            if (j1 < NB){ float a=Ld[j1][k]; float ap=Ld[j1][k+1]-a*tco; c1v=a*ivk; e1v=ap*ivk1; }
            for (int i = k+1+ty; i < NB; i += 16) {
                float aik = Ld[i][k], aik1 = Ld[i][k+1];
                float api = aik1 - aik*tco;
                if (tx == 0) colbuf[i][b] = api;
                if (j0 <= i) Ld[i][j0] -= aik*c0v + api*e0v;
                if (j1 <= i) Ld[i][j1] -= aik*c1v + api*e1v;
            }
            __syncthreads();
        }
        // restore odd columns (final values) from colbuf
        for (int t2 = tid; t2 < NB*(NB/2); t2 += NT) {
            int i = t2 >> 5, b = t2 & 31;
            int j = 2*b+1;
            if (i >= j) Ld[i][j] = colbuf[i][b];
        }
        __syncthreads();
        // scaling: pivots -> dinv/log; scale strictly-lower columns
        if (tid < NB) {
            float v = Ld[tid][tid];
            if (p == NPAN-1 && tid == NB-1) { s_quad = v; dinv[tid] = 1.f; }
            else { dinv[tid] = rsqrtf(v); logsum += logf(v); }   // log d_k
        }
        __syncthreads();
        for (int t2 = tid; t2 < NB*NB; t2 += NT) {
            int i = t2 >> 6, j = t2 & 63;
            if (i > j) Ld[i][j] *= dinv[j];
        }
        __syncthreads();

        // --- blocked right-looking TRSM: CTA `rank` owns row panel p+1+rank
        int r = p + 1 + rank;
        if (r < NPAN) {
            int r0 = r*NB;
            for (int t2 = tid; t2 < NB*16; t2 += NT) {
                int i = t2 >> 4, j4 = (t2 & 15) << 2;
                float4 v = __ldcg((const float4*)&g_S[(r0+i)*MP + c0 + j4]);
                Bs[i][j4]=v.x; Bs[i][j4+1]=v.y; Bs[i][j4+2]=v.z; Bs[i][j4+3]=v.w;
            }
            __syncthreads();
            int row = tid & 63, qq = tid >> 6;   // 8 col-streams
            #pragma unroll 1
            for (int blk = 0; blk < 8; blk++) {
                int cb = blk*8;
                if (tid < NB) {   // serial solve within 8-column block
                    #pragma unroll
                    for (int jj = 0; jj < 8; jj++) {
                        int j = cb + jj;
                        float a = Bs[tid][j];
                        for (int c = cb; c < j; c++) a -= Bs[tid][c]*Ld[j][c];
                        Bs[tid][j] = a * dinv[j];
                    }
                }
                __syncthreads();
                if (blk < 7) {    // parallel update of later columns
                    float rb[8];
                    #pragma unroll
                    for (int c = 0; c < 8; c++) rb[c] = Bs[row][cb+c];
                    for (int j = cb+8+qq; j < NB; j += 8) {
                        float s = 0.f;
                        #pragma unroll
                        for (int c = 0; c < 8; c++) s += rb[c]*Ld[j][cb+c];
                        Bs[row][j] -= s;
                    }
                    __syncthreads();
                }
            }
            for (int t2 = tid; t2 < NB*16; t2 += NT) {
                int i = t2 >> 4, j4 = (t2 & 15) << 2;
                float4 v = make_float4(Bs[i][j4],Bs[i][j4+1],Bs[i][j4+2],Bs[i][j4+3]);
                *(float4*)&g_S[(r0+i)*MP + c0 + j4] = v;
            }
        }

        if (p < NPAN-1) {
            __threadfence(); CLUSTER_SYNC();
            // --- SYRK trailing update, tiles distributed over cluster ---
            int T = NPAN-1-p;
            int ntiles = T*(T+1)/2;
            for (int t0 = rank; t0 < ntiles; t0 += CL) {
                int idx = t0, bi = 0;
                while (idx >= bi+1){ idx -= bi+1; bi++; }
                int bj = idx;
                int rI = (p+1+bi)*NB, rJ = (p+1+bj)*NB;
                for (int t2 = tid; t2 < NB*16; t2 += NT) {
                    int i = t2 >> 4, j4 = (t2 & 15) << 2;
                    float4 v = __ldcg((const float4*)&g_S[(rI+i)*MP + c0 + j4]);
                    Ld[i][j4]=v.x; Ld[i][j4+1]=v.y; Ld[i][j4+2]=v.z; Ld[i][j4+3]=v.w;
                }
                if (bi != bj) {
                    for (int t2 = tid; t2 < NB*16; t2 += NT) {
                        int i = t2 >> 4, j4 = (t2 & 15) << 2;
                        float4 v = __ldcg((const float4*)&g_S[(rJ+i)*MP + c0 + j4]);
                        Bs[i][j4]=v.x; Bs[i][j4+1]=v.y; Bs[i][j4+2]=v.z; Bs[i][j4+3]=v.w;
                    }
                }
                __syncthreads();
                float (*Lj)[NB+1] = (bi==bj) ? Ld : Bs;
                // 512 threads: 16 cols-of-4 x 32 rows-of-2
                int sx = tid & 15, sy = tid >> 4;
                float acc[2][4] = {};
                #pragma unroll 4
                for (int kk = 0; kk < NB; kk++) {
                    float av[2], bv[4];
                    av[0]=Ld[sy*2][kk]; av[1]=Ld[sy*2+1][kk];
                    #pragma unroll
                    for (int v2=0;v2<4;v2++) bv[v2]=Lj[sx*4+v2][kk];
                    #pragma unroll
                    for (int u=0;u<2;u++)
                        #pragma unroll
                        for (int v2=0;v2<4;v2++) acc[u][v2] += av[u]*bv[v2];
                }
                #pragma unroll
                for (int u=0;u<2;u++) {
                    float* ptr = &g_S[(rI+sy*2+u)*MP + rJ + sx*4];
                    float4 old = __ldcg((const float4*)ptr);
                    old.x -= acc[u][0]; old.y -= acc[u][1];
                    old.z -= acc[u][2]; old.w -= acc[u][3];
                    *(float4*)ptr = old;
                }
                __syncthreads();
            }
            __threadfence(); CLUSTER_SYNC();
        }
    }

    // ---------------- epilogue: loss (rank 0) ------------------------------
    if (rank == 0) {
        if (tid < NB) dinv[tid] = logsum;
        __syncthreads();
        if (tid == 0) {
            float l = 0.f;
            for (int k2 = 0; k2 < NB; k2++) l += dinv[k2];   // logdet S
            double quad1 = -(double)s_quad;
            double ed = (double)e;
            double rTrv = __ldcg(&g_rTr);
            double ldD0v = __ldcg(&g_ldD0);
            double q0v  = __ldcg(&g_q0);
            double logdetV = (double)(n - (NQ0 + NQ1)) * log(ed) + ldD0v + (double)l;
            double quad = (rTrv - q0v - quad1) / ed;
            double loss = 0.5 * (double)n * 1.8378770664093454836
                        + 0.5 * logdetV + 0.5 * quad;
            out[0] = (float)loss;
        }
    }
}

// ---------------- host launcher --------------------------------------------
extern "C" void kernel_launch(void* const* d_in, const int* in_sizes, int n_in,
                              void* d_out, int out_size) {
    const float* y_true = (const float*)d_in[0];
    const float* y_pred = (const float*)d_in[1];
    const void*  z0     = d_in[2];
    const void*  z1     = d_in[3];
    const float* sig2e  = (const float*)d_in[4];
    const float* sig2bs = (const float*)d_in[5];
    float* out = (float*)d_out;
    int n = in_sizes[0];

    k_all<<<CL, NT>>>(y_true, y_pred, z0, z1, sig2e, sig2bs, out, n);
}